// round 1
// baseline (speedup 1.0000x reference)
#include <cuda_runtime.h>
#include <cuda_bf16.h>
#include <math.h>

#define Nn   16000
#define Ee   48000
#define Ff   32000
#define Dd   64
#define Bb   32
#define Gg   32
#define HIDN 256
#define NCc  10
#define SCALEF 100.0f

#define DSLICE 4
#define NSLICE (Dd / DSLICE)          // 16
#define CHUNKS 40
#define M_TOTAL (Nn + Ee + Ff)        // 96000
#define ITEMS_PER_CHUNK ((M_TOTAL + CHUNKS - 1) / CHUNKS)  // 2400

// scratch (device globals: no allocations allowed)
__device__ float d_nh[Nn * Dd];                    // 4 MB: per-node heights
__device__ float d_sig[Gg * Bb * Dd];              // windowed-sigmoid partials
__device__ float d_step[Gg * (Bb + 1) * Dd];       // step deltas (prefix-summed later)

__global__ void zero_kernel() {
    int i = blockIdx.x * blockDim.x + threadIdx.x;
    if (i < Gg * Bb * Dd) d_sig[i] = 0.f;
    if (i < Gg * (Bb + 1) * Dd) d_step[i] = 0.f;
}

__global__ void nh_kernel(const float* __restrict__ x, const float* __restrict__ nw,
                          const float* __restrict__ v) {
    int i = blockIdx.x * blockDim.x + threadIdx.x;
    if (i >= Nn * Dd) return;
    int n = i >> 6, d = i & 63;
    float w = nw[n];
    float h = w * (x[n * 3 + 0] * v[d] +
                   x[n * 3 + 1] * v[Dd + d] +
                   x[n * 3 + 2] * v[2 * Dd + d]);
    d_nh[i] = h;
}

__device__ __forceinline__ int clampi(int a, int lo, int hi) {
    return a < lo ? lo : (a > hi ? hi : a);
}

__global__ void __launch_bounds__(256) ecc_kernel(
    const float* __restrict__ ew, const float* __restrict__ fw,
    const int* __restrict__ eidx, const int* __restrict__ fidx,
    const int* __restrict__ batch)
{
    __shared__ float s_sig[Gg * Bb * DSLICE];          // 16 KB
    __shared__ float s_step[Gg * (Bb + 1) * DSLICE];   // 16.5 KB
    const int tid = threadIdx.x;
    for (int i = tid; i < Gg * Bb * DSLICE; i += 256) s_sig[i] = 0.f;
    for (int i = tid; i < Gg * (Bb + 1) * DSLICE; i += 256) s_step[i] = 0.f;
    __syncthreads();

    const int slice = blockIdx.y;
    const int dloc  = tid & (DSLICE - 1);
    const int dglob = slice * DSLICE + dloc;
    const int itemoff = tid >> 2;                      // 0..63
    const int base = blockIdx.x * ITEMS_PER_CHUNK;
    const int iend = min(M_TOTAL, base + ITEMS_PER_CHUNK);

    const float dl = 2.f / 31.f;
    const float inv_dl = 31.f * 0.5f;

    for (int id = base + itemoff; id < iend; id += 64) {
        float h, sign; int g;
        if (id < Nn) {
            h = d_nh[id * Dd + dglob];
            g = batch[id];
            sign = 1.f;
        } else if (id < Nn + Ee) {
            int e = id - Nn;
            int a = clampi(eidx[e], 0, Nn - 1);
            int b = clampi(eidx[Ee + e], 0, Nn - 1);
            h = fmaxf(d_nh[a * Dd + dglob], d_nh[b * Dd + dglob]) * ew[e];
            g = batch[a];
            sign = -1.f;
        } else {
            int f = id - Nn - Ee;
            int a = clampi(fidx[f], 0, Nn - 1);
            int b = clampi(fidx[Ff + f], 0, Nn - 1);
            int c = clampi(fidx[2 * Ff + f], 0, Nn - 1);
            h = fmaxf(fmaxf(d_nh[a * Dd + dglob], d_nh[b * Dd + dglob]),
                      d_nh[c * Dd + dglob]) * fw[f];
            g = batch[a];
            sign = 1.f;
        }
        g = clampi(g, 0, Gg - 1);

        // crossing position in bump space; sigmoid non-saturated only within ±3.2 bumps
        float t = (h + 1.f) * inv_dl;
        int b_end = clampi((int)floorf(t + 3.2f) + 1, 0, Bb);
        int b_start = max(0, (int)ceilf(t - 3.2f));
        for (int b = b_start; b < b_end; ++b) {
            float arg = SCALEF * (fmaf((float)b, dl, -1.f) - h);
            float s = __fdividef(1.f, 1.f + __expf(-arg));
            atomicAdd(&s_sig[(g * Bb + b) * DSLICE + dloc], sign * s);
        }
        // every bump >= b_end contributes ~1.0 -> record one delta (slot Bb is a trash slot)
        atomicAdd(&s_step[(g * (Bb + 1) + b_end) * DSLICE + dloc], sign);
    }
    __syncthreads();

    // flush block partials (skip zeros)
    for (int i = tid; i < Gg * Bb * DSLICE; i += 256) {
        float vsum = s_sig[i];
        if (vsum != 0.f) {
            int d0 = i & (DSLICE - 1);
            int gb = i / DSLICE;
            atomicAdd(&d_sig[gb * Dd + slice * DSLICE + d0], vsum);
        }
    }
    for (int i = tid; i < Gg * (Bb + 1) * DSLICE; i += 256) {
        float vsum = s_step[i];
        if (vsum != 0.f) {
            int d0 = i & (DSLICE - 1);
            int gb = i / DSLICE;
            atomicAdd(&d_step[gb * Dd + slice * DSLICE + d0], vsum);
        }
    }
}

// prefix over bumps: ecc[g][b][d] = sig[g][b][d] + sum_{b'<=b} step[g][b'][d]
__global__ void combine_kernel(float* __restrict__ flat) {
    int idx = blockIdx.x * blockDim.x + threadIdx.x;
    if (idx >= Gg * Dd) return;
    int g = idx / Dd, d = idx % Dd;
    float run = 0.f;
    for (int b = 0; b < Bb; ++b) {
        run += d_step[(g * (Bb + 1) + b) * Dd + d];
        flat[(g * Bb + b) * Dd + d] = d_sig[(g * Bb + b) * Dd + d] + run;
    }
}

__global__ void __launch_bounds__(HIDN) mlp_kernel(
    const float* __restrict__ flat, const float* __restrict__ W1,
    const float* __restrict__ b1, const float* __restrict__ W2,
    const float* __restrict__ b2, float* __restrict__ logits)
{
    __shared__ float sf[Bb * Dd];     // 8 KB: this graph's flat vector
    __shared__ float sh[HIDN];
    const int g = blockIdx.x, j = threadIdx.x;
    for (int i = j; i < Bb * Dd; i += HIDN) sf[i] = flat[g * Bb * Dd + i];
    __syncthreads();

    float acc = b1[j];
    const float4* wr = (const float4*)(W1 + (size_t)j * (Bb * Dd));
    #pragma unroll 8
    for (int k = 0; k < (Bb * Dd) / 4; ++k) {
        float4 w = wr[k];
        float4 f4 = *(const float4*)&sf[k * 4];
        acc = fmaf(w.x, f4.x, acc);
        acc = fmaf(w.y, f4.y, acc);
        acc = fmaf(w.z, f4.z, acc);
        acc = fmaf(w.w, f4.w, acc);
    }
    sh[j] = fmaxf(acc, 0.f);
    __syncthreads();

    if (j < NCc) {
        float a = b2[j];
        #pragma unroll 8
        for (int k = 0; k < HIDN; ++k) a = fmaf(sh[k], W2[j * HIDN + k], a);
        logits[g * NCc + j] = a;
    }
}

extern "C" void kernel_launch(void* const* d_in, const int* in_sizes, int n_in,
                              void* d_out, int out_size) {
    const float* x   = (const float*)d_in[0];
    const float* nw  = (const float*)d_in[1];
    const float* ew  = (const float*)d_in[2];
    const float* fw  = (const float*)d_in[3];
    const float* v   = (const float*)d_in[4];
    const float* W1  = (const float*)d_in[5];
    const float* b1  = (const float*)d_in[6];
    const float* W2  = (const float*)d_in[7];
    const float* b2  = (const float*)d_in[8];
    const int* eidx  = (const int*)d_in[9];
    const int* fidx  = (const int*)d_in[10];
    const int* batch = (const int*)d_in[11];

    float* out = (float*)d_out;
    float* logits = out;                 // [32, 10]
    float* flat   = out + Gg * NCc;      // [32, 2048]

    zero_kernel<<<(Gg * (Bb + 1) * Dd + 255) / 256, 256>>>();
    nh_kernel<<<(Nn * Dd + 255) / 256, 256>>>(x, nw, v);
    dim3 grid(CHUNKS, NSLICE);
    ecc_kernel<<<grid, 256>>>(ew, fw, eidx, fidx, batch);
    combine_kernel<<<(Gg * Dd + 255) / 256, 256>>>(flat);
    mlp_kernel<<<Gg, HIDN>>>(flat, W1, b1, W2, b2, logits);
}

// round 2
// speedup vs baseline: 1.0967x; 1.0967x over previous
#include <cuda_runtime.h>
#include <cuda_bf16.h>
#include <math.h>

#define Nn   16000
#define Ee   48000
#define Ff   32000
#define Dd   64
#define Bb   32
#define Gg   32
#define HIDN 256
#define NCc  10

#define DSLICE 4
#define NSLICE (Dd / DSLICE)          // 16
#define CHUNKS 40
#define M_TOTAL (Nn + Ee + Ff)        // 96000
#define ITEMS_PER_CHUNK ((M_TOTAL + CHUNKS - 1) / CHUNKS)  // 2400

// c = SCALE * dl = 100 * (2/31); half of it for tanh form
#define C_HALF 3.2258064516f
#define WIN 2.25f

// scratch (device globals: no allocations allowed)
__device__ float d_nh[Nn * Dd];                    // 4 MB: per-node heights
__device__ float d_sig[Gg * Bb * Dd];              // windowed-sigmoid partials
__device__ float d_step[Gg * (Bb + 1) * Dd];       // step deltas

// fused: zero accumulators + compute node heights (vectorized over 4 dirs)
__global__ void init_kernel(const float* __restrict__ x, const float* __restrict__ nw,
                            const float* __restrict__ v) {
    int i = blockIdx.x * blockDim.x + threadIdx.x;
    if (i < Gg * Bb * Dd) d_sig[i] = 0.f;
    if (i < Gg * (Bb + 1) * Dd) d_step[i] = 0.f;
    if (i >= Nn * (Dd / 4)) return;
    int n = i >> 4, q = i & 15;                     // q: which float4 of 64 dirs
    float w = nw[n];
    float x0 = x[n * 3 + 0] * w, x1 = x[n * 3 + 1] * w, x2 = x[n * 3 + 2] * w;
    float4 v0 = ((const float4*)(v))[q];
    float4 v1 = ((const float4*)(v + Dd))[q];
    float4 v2 = ((const float4*)(v + 2 * Dd))[q];
    float4 r;
    r.x = x0 * v0.x + x1 * v1.x + x2 * v2.x;
    r.y = x0 * v0.y + x1 * v1.y + x2 * v2.y;
    r.z = x0 * v0.z + x1 * v1.z + x2 * v2.z;
    r.w = x0 * v0.w + x1 * v1.w + x2 * v2.w;
    ((float4*)d_nh)[i] = r;
}

__device__ __forceinline__ float fast_tanh(float u) {
    float r;
    asm("tanh.approx.f32 %0, %1;" : "=f"(r) : "f"(u));
    return r;
}

__global__ void __launch_bounds__(256) ecc_kernel(
    const float* __restrict__ ew, const float* __restrict__ fw,
    const int* __restrict__ eidx, const int* __restrict__ fidx,
    const int* __restrict__ batch)
{
    __shared__ float s_sig[Gg * Bb * DSLICE];          // 16 KB
    __shared__ float s_step[Gg * (Bb + 1) * DSLICE];   // 16.5 KB
    const int tid = threadIdx.x;
    for (int i = tid; i < Gg * Bb * DSLICE; i += 256) s_sig[i] = 0.f;
    for (int i = tid; i < Gg * (Bb + 1) * DSLICE; i += 256) s_step[i] = 0.f;
    __syncthreads();

    const int slice = blockIdx.y;
    const int dloc  = tid & (DSLICE - 1);
    const int dglob = slice * DSLICE + dloc;
    const int itemoff = tid >> 2;                      // 0..63
    const int base = blockIdx.x * ITEMS_PER_CHUNK;
    const int iend = min(M_TOTAL, base + ITEMS_PER_CHUNK);

    const float inv_dl = 31.f * 0.5f;

    for (int id = base + itemoff; id < iend; id += 64) {
        float h, sign; int g;
        if (id < Nn) {
            h = d_nh[id * Dd + dglob];
            g = batch[id];
            sign = 1.f;
        } else if (id < Nn + Ee) {
            int e = id - Nn;
            int a = eidx[e];
            int b = eidx[Ee + e];
            h = fmaxf(d_nh[a * Dd + dglob], d_nh[b * Dd + dglob]) * ew[e];
            g = batch[a];
            sign = -1.f;
        } else {
            int f = id - Nn - Ee;
            int a = fidx[f];
            int b = fidx[Ff + f];
            int c = fidx[2 * Ff + f];
            h = fmaxf(fmaxf(d_nh[a * Dd + dglob], d_nh[b * Dd + dglob]),
                      d_nh[c * Dd + dglob]) * fw[f];
            g = batch[a];
            sign = 1.f;
        }

        // crossing position in bump space
        float t = fmaf(h, inv_dl, inv_dl);
        int b0 = (int)ceilf(t - WIN);
        int be = (int)floorf(t + WIN) + 1;
        int bstart = max(b0, 0);
        int bstop  = min(be, Bb);
        int bend_c = min(max(be, 0), Bb);

        float shalf = 0.5f * sign;
        float u = ((float)bstart - t) * C_HALF;
        float* sig_base = &s_sig[(g * Bb) * DSLICE + dloc];
        #pragma unroll
        for (int j = 0; j < 5; ++j) {
            int b = bstart + j;
            if (b < bstop) {
                float val = fmaf(shalf, fast_tanh(u), shalf);
                atomicAdd(sig_base + b * DSLICE, val);
            }
            u += C_HALF;
        }
        atomicAdd(&s_step[(g * (Bb + 1) + bend_c) * DSLICE + dloc], sign);
    }
    __syncthreads();

    // flush block partials (skip zeros)
    for (int i = tid; i < Gg * Bb * DSLICE; i += 256) {
        float vsum = s_sig[i];
        if (vsum != 0.f) {
            int d0 = i & (DSLICE - 1);
            int gb = i / DSLICE;
            atomicAdd(&d_sig[gb * Dd + slice * DSLICE + d0], vsum);
        }
    }
    for (int i = tid; i < Gg * (Bb + 1) * DSLICE; i += 256) {
        float vsum = s_step[i];
        if (vsum != 0.f) {
            int d0 = i & (DSLICE - 1);
            int gb = i / DSLICE;
            atomicAdd(&d_step[gb * Dd + slice * DSLICE + d0], vsum);
        }
    }
}

// prefix over bumps: ecc[g][b][d] = sig[g][b][d] + sum_{b'<=b} step[g][b'][d]
__global__ void combine_kernel(float* __restrict__ flat) {
    int g = blockIdx.x;
    int d = threadIdx.x;                // 64 threads
    float run = 0.f;
    for (int b = 0; b < Bb; ++b) {
        run += d_step[(g * (Bb + 1) + b) * Dd + d];
        flat[(g * Bb + b) * Dd + d] = d_sig[(g * Bb + b) * Dd + d] + run;
    }
}

__global__ void __launch_bounds__(HIDN) mlp_kernel(
    const float* __restrict__ flat, const float* __restrict__ W1,
    const float* __restrict__ b1, const float* __restrict__ W2,
    const float* __restrict__ b2, float* __restrict__ logits)
{
    __shared__ float sf[Bb * Dd];     // 8 KB: this graph's flat vector
    __shared__ float sh[HIDN];
    const int g = blockIdx.x, j = threadIdx.x;
    for (int i = j; i < Bb * Dd; i += HIDN) sf[i] = flat[g * Bb * Dd + i];
    __syncthreads();

    float acc = b1[j];
    const float4* wr = (const float4*)(W1 + (size_t)j * (Bb * Dd));
    #pragma unroll 8
    for (int k = 0; k < (Bb * Dd) / 4; ++k) {
        float4 w = wr[k];
        float4 f4 = *(const float4*)&sf[k * 4];
        acc = fmaf(w.x, f4.x, acc);
        acc = fmaf(w.y, f4.y, acc);
        acc = fmaf(w.z, f4.z, acc);
        acc = fmaf(w.w, f4.w, acc);
    }
    sh[j] = fmaxf(acc, 0.f);
    __syncthreads();

    if (j < NCc) {
        float a = b2[j];
        #pragma unroll 8
        for (int k = 0; k < HIDN; ++k) a = fmaf(sh[k], W2[j * HIDN + k], a);
        logits[g * NCc + j] = a;
    }
}

extern "C" void kernel_launch(void* const* d_in, const int* in_sizes, int n_in,
                              void* d_out, int out_size) {
    const float* x   = (const float*)d_in[0];
    const float* nw  = (const float*)d_in[1];
    const float* ew  = (const float*)d_in[2];
    const float* fw  = (const float*)d_in[3];
    const float* v   = (const float*)d_in[4];
    const float* W1  = (const float*)d_in[5];
    const float* b1  = (const float*)d_in[6];
    const float* W2  = (const float*)d_in[7];
    const float* b2  = (const float*)d_in[8];
    const int* eidx  = (const int*)d_in[9];
    const int* fidx  = (const int*)d_in[10];
    const int* batch = (const int*)d_in[11];

    float* out = (float*)d_out;
    float* logits = out;                 // [32, 10]
    float* flat   = out + Gg * NCc;      // [32, 2048]

    init_kernel<<<(Nn * (Dd / 4) + 255) / 256, 256>>>(x, nw, v);
    dim3 grid(CHUNKS, NSLICE);
    ecc_kernel<<<grid, 256>>>(ew, fw, eidx, fidx, batch);
    combine_kernel<<<Gg, Dd>>>(flat);
    mlp_kernel<<<Gg, HIDN>>>(flat, W1, b1, W2, b2, logits);
}

// round 5
// speedup vs baseline: 1.3784x; 1.2568x over previous
#include <cuda_runtime.h>
#include <cuda_bf16.h>
#include <math.h>

#define Nn   16000
#define Ee   48000
#define Ff   32000
#define Dd   64
#define Bb   32
#define Gg   32
#define HIDN 256
#define NCc  10

#define DSLICE 4
#define NSLICE (Dd / DSLICE)          // 16
#define CHUNKS 40
#define M_TOTAL (Nn + Ee + Ff)        // 96000
#define ITEMS_PER_CHUNK ((M_TOTAL + CHUNKS - 1) / CHUNKS)  // 2400

#define C_HALF 3.2258064516f          // 0.5 * SCALE * (2/31)
#define WIN 2.25f

#define KC 8                           // k-chunks (4 bumps each)
#define JG 32                          // j-groups (8 hidden each)
#define FPAD 4
#define FSTRIDE (256 + FPAD)           // padded flat-tile row stride (floats)

// scratch (device globals: no allocations allowed)
__device__ float d_nh[Nn * Dd];                    // 4 MB: per-node heights
__device__ float d_sig[Gg * Bb * Dd];              // windowed-sigmoid partials
__device__ float d_step[Gg * (Bb + 1) * Dd];       // step deltas
__device__ float d_h[Gg * HIDN];                   // hidden pre-activations

// fused: zero accumulators + seed d_h with b1 + compute node heights
__global__ void init_kernel(const float* __restrict__ x, const float* __restrict__ nw,
                            const float* __restrict__ v, const float* __restrict__ b1) {
    int i = blockIdx.x * blockDim.x + threadIdx.x;
    if (i < Gg * Bb * Dd) d_sig[i] = 0.f;
    if (i < Gg * (Bb + 1) * Dd) d_step[i] = 0.f;
    if (i < Gg * HIDN) d_h[i] = b1[i & (HIDN - 1)];
    if (i >= Nn * (Dd / 4)) return;
    int n = i >> 4, q = i & 15;
    float w = nw[n];
    float x0 = x[n * 3 + 0] * w, x1 = x[n * 3 + 1] * w, x2 = x[n * 3 + 2] * w;
    float4 v0 = ((const float4*)(v))[q];
    float4 v1 = ((const float4*)(v + Dd))[q];
    float4 v2 = ((const float4*)(v + 2 * Dd))[q];
    float4 r;
    r.x = x0 * v0.x + x1 * v1.x + x2 * v2.x;
    r.y = x0 * v0.y + x1 * v1.y + x2 * v2.y;
    r.z = x0 * v0.z + x1 * v1.z + x2 * v2.z;
    r.w = x0 * v0.w + x1 * v1.w + x2 * v2.w;
    ((float4*)d_nh)[i] = r;
}

__device__ __forceinline__ float fast_tanh(float u) {
    float r;
    asm("tanh.approx.f32 %0, %1;" : "=f"(r) : "f"(u));
    return r;
}

__global__ void __launch_bounds__(256) ecc_kernel(
    const float* __restrict__ ew, const float* __restrict__ fw,
    const int* __restrict__ eidx, const int* __restrict__ fidx,
    const int* __restrict__ batch)
{
    __shared__ float s_sig[Gg * Bb * DSLICE];          // 16 KB
    __shared__ float s_step[Gg * (Bb + 1) * DSLICE];   // 16.5 KB
    const int tid = threadIdx.x;
    for (int i = tid; i < Gg * Bb * DSLICE; i += 256) s_sig[i] = 0.f;
    for (int i = tid; i < Gg * (Bb + 1) * DSLICE; i += 256) s_step[i] = 0.f;
    __syncthreads();

    const int slice = blockIdx.y;
    const int dloc  = tid & (DSLICE - 1);
    const int dglob = slice * DSLICE + dloc;
    const int itemoff = tid >> 2;                      // 0..63
    const int base = blockIdx.x * ITEMS_PER_CHUNK;
    const int iend = min(M_TOTAL, base + ITEMS_PER_CHUNK);

    const float inv_dl = 31.f * 0.5f;

    for (int id = base + itemoff; id < iend; id += 64) {
        float h, sign; int g;
        if (id < Nn) {
            h = d_nh[id * Dd + dglob];
            g = batch[id];
            sign = 1.f;
        } else if (id < Nn + Ee) {
            int e = id - Nn;
            int a = eidx[e];
            int b = eidx[Ee + e];
            h = fmaxf(d_nh[a * Dd + dglob], d_nh[b * Dd + dglob]) * ew[e];
            g = batch[a];
            sign = -1.f;
        } else {
            int f = id - Nn - Ee;
            int a = fidx[f];
            int b = fidx[Ff + f];
            int c = fidx[2 * Ff + f];
            h = fmaxf(fmaxf(d_nh[a * Dd + dglob], d_nh[b * Dd + dglob]),
                      d_nh[c * Dd + dglob]) * fw[f];
            g = batch[a];
            sign = 1.f;
        }

        float t = fmaf(h, inv_dl, inv_dl);
        int b0 = (int)ceilf(t - WIN);
        int be = (int)floorf(t + WIN) + 1;
        int bstart = max(b0, 0);
        int bstop  = min(be, Bb);
        int bend_c = min(max(be, 0), Bb);

        float shalf = 0.5f * sign;
        float u = ((float)bstart - t) * C_HALF;
        float* sig_base = &s_sig[(g * Bb) * DSLICE + dloc];
        #pragma unroll
        for (int j = 0; j < 5; ++j) {
            int b = bstart + j;
            if (b < bstop) {
                float val = fmaf(shalf, fast_tanh(u), shalf);
                atomicAdd(sig_base + b * DSLICE, val);
            }
            u += C_HALF;
        }
        atomicAdd(&s_step[(g * (Bb + 1) + bend_c) * DSLICE + dloc], sign);
    }
    __syncthreads();

    for (int i = tid; i < Gg * Bb * DSLICE; i += 256) {
        float vsum = s_sig[i];
        if (vsum != 0.f) {
            int d0 = i & (DSLICE - 1);
            int gb = i / DSLICE;
            atomicAdd(&d_sig[gb * Dd + slice * DSLICE + d0], vsum);
        }
    }
    for (int i = tid; i < Gg * (Bb + 1) * DSLICE; i += 256) {
        float vsum = s_step[i];
        if (vsum != 0.f) {
            int d0 = i & (DSLICE - 1);
            int gb = i / DSLICE;
            atomicAdd(&d_step[gb * Dd + slice * DSLICE + d0], vsum);
        }
    }
}

// fused combine + first GEMM layer, split-K over bump chunks.
// grid: (KC, JG); block 256.  Each block: 4 bumps (256 k) x 8 hidden x 32 graphs.
__global__ void __launch_bounds__(256) mlp1_kernel(
    const float* __restrict__ W1, float* __restrict__ flat)
{
    __shared__ float s_f[Gg * FSTRIDE];    // 32 x (256+4) floats = 33.3 KB
    __shared__ float s_w[8 * 256];         // 8 KB
    const int tid = threadIdx.x;
    const int kc = blockIdx.x;             // bump-chunk: bumps [kc*4, kc*4+4)
    const int jg = blockIdx.y;             // hidden units [jg*8, jg*8+8)
    const int bb0 = kc * 4;

    // --- step 1: reconstruct flat chunk (combine) into smem ---
    {
        int g = tid >> 3;
        int d0 = (tid & 7) * 8;
        #pragma unroll
        for (int dd = 0; dd < 8; ++dd) {
            int d = d0 + dd;
            const float* stp = &d_step[(g * (Bb + 1)) * Dd + d];
            float run = 0.f;
            for (int b = 0; b < bb0; ++b) run += stp[b * Dd];
            #pragma unroll
            for (int bi = 0; bi < 4; ++bi) {
                int b = bb0 + bi;
                run += stp[b * Dd];
                float val = d_sig[(g * Bb + b) * Dd + d] + run;
                s_f[g * FSTRIDE + bi * Dd + d] = val;
                if (jg == 0) flat[(g * Bb + b) * Dd + d] = val;
            }
        }
    }

    // --- step 2: load W1 tile (8 rows x 256 cols slice) ---
    {
        const int koff = bb0 * Dd;         // = kc*256
        #pragma unroll
        for (int r = 0; r < 2; ++r) {
            int idx = tid + r * 256;       // float4 index within 8x256 tile
            int row = idx >> 6, col = (idx & 63) << 2;
            ((float4*)s_w)[idx] = *(const float4*)&W1[(size_t)(jg * 8 + row) * (Bb * Dd) + koff + col];
        }
    }
    __syncthreads();

    // --- step 3: per-thread dot over 256 k ---
    const int j = tid >> 5;                // 0..7 (warp-uniform)
    const int g = tid & 31;                // lane
    const float4* wrow = (const float4*)&s_w[j * 256];
    const float* frow = &s_f[g * FSTRIDE];
    float acc = 0.f;
    #pragma unroll 8
    for (int k4 = 0; k4 < 64; ++k4) {
        float4 w = wrow[k4];
        float4 f = *(const float4*)&frow[k4 * 4];
        acc = fmaf(w.x, f.x, acc);
        acc = fmaf(w.y, f.y, acc);
        acc = fmaf(w.z, f.z, acc);
        acc = fmaf(w.w, f.w, acc);
    }
    atomicAdd(&d_h[g * HIDN + jg * 8 + j], acc);
}

// relu + second layer
__global__ void __launch_bounds__(HIDN) mlp2_kernel(
    const float* __restrict__ W2, const float* __restrict__ b2,
    float* __restrict__ logits)
{
    __shared__ float sh[HIDN];
    const int g = blockIdx.x, j = threadIdx.x;
    sh[j] = fmaxf(d_h[g * HIDN + j], 0.f);
    __syncthreads();
    if (j < NCc) {
        float a = b2[j];
        #pragma unroll 8
        for (int k = 0; k < HIDN; ++k) a = fmaf(sh[k], W2[j * HIDN + k], a);
        logits[g * NCc + j] = a;
    }
}

extern "C" void kernel_launch(void* const* d_in, const int* in_sizes, int n_in,
                              void* d_out, int out_size) {
    const float* x   = (const float*)d_in[0];
    const float* nw  = (const float*)d_in[1];
    const float* ew  = (const float*)d_in[2];
    const float* fw  = (const float*)d_in[3];
    const float* v   = (const float*)d_in[4];
    const float* W1  = (const float*)d_in[5];
    const float* b1  = (const float*)d_in[6];
    const float* W2  = (const float*)d_in[7];
    const float* b2  = (const float*)d_in[8];
    const int* eidx  = (const int*)d_in[9];
    const int* fidx  = (const int*)d_in[10];
    const int* batch = (const int*)d_in[11];

    float* out = (float*)d_out;
    float* logits = out;                 // [32, 10]
    float* flat   = out + Gg * NCc;      // [32, 2048]

    init_kernel<<<(Nn * (Dd / 4) + 255) / 256, 256>>>(x, nw, v, b1);
    dim3 grid(CHUNKS, NSLICE);
    ecc_kernel<<<grid, 256>>>(ew, fw, eidx, fidx, batch);
    dim3 mgrid(KC, JG);
    mlp1_kernel<<<mgrid, 256>>>(W1, flat);
    mlp2_kernel<<<Gg, HIDN>>>(W2, b2, logits);
}

// round 7
// speedup vs baseline: 1.5307x; 1.1105x over previous
#include <cuda_runtime.h>
#include <cuda_bf16.h>
#include <math.h>

#define Nn   16000
#define Ee   48000
#define Ff   32000
#define Dd   64
#define Bb   32
#define Gg   32
#define HIDN 256
#define NCc  10

#define DSLICE 4
#define NSLICE (Dd / DSLICE)          // 16
#define CHUNKS 40
#define M_TOTAL (Nn + Ee + Ff)        // 96000
#define ITEMS_PER_CHUNK ((M_TOTAL + CHUNKS - 1) / CHUNKS)  // 2400

#define C_HALF 3.2258064516f          // 0.5 * SCALE * (2/31)

#define KC 8                           // k-chunks (4 bumps each)
#define JG 32                          // j-groups (8 hidden each)
#define FPAD 4
#define FSTRIDE (256 + FPAD)           // padded flat-tile row stride (floats)

// scratch (device globals: no allocations allowed)
__device__ float d_nh[Nn * Dd];                    // 4 MB: per-node heights
__device__ float d_sig[Gg * Bb * Dd];              // windowed-sigmoid partials
__device__ float d_step[Gg * (Bb + 1) * Dd];       // step deltas
__device__ float d_h[Gg * HIDN];                   // hidden pre-activations

// fused: zero accumulators + seed d_h with b1 + compute node heights
__global__ void init_kernel(const float* __restrict__ x, const float* __restrict__ nw,
                            const float* __restrict__ v, const float* __restrict__ b1) {
    int i = blockIdx.x * blockDim.x + threadIdx.x;
    if (i < Gg * Bb * Dd) d_sig[i] = 0.f;
    if (i < Gg * (Bb + 1) * Dd) d_step[i] = 0.f;
    if (i < Gg * HIDN) d_h[i] = b1[i & (HIDN - 1)];
    if (i >= Nn * (Dd / 4)) return;
    int n = i >> 4, q = i & 15;
    float w = nw[n];
    float x0 = x[n * 3 + 0] * w, x1 = x[n * 3 + 1] * w, x2 = x[n * 3 + 2] * w;
    float4 v0 = ((const float4*)(v))[q];
    float4 v1 = ((const float4*)(v + Dd))[q];
    float4 v2 = ((const float4*)(v + 2 * Dd))[q];
    float4 r;
    r.x = x0 * v0.x + x1 * v1.x + x2 * v2.x;
    r.y = x0 * v0.y + x1 * v1.y + x2 * v2.y;
    r.z = x0 * v0.z + x1 * v1.z + x2 * v2.z;
    r.w = x0 * v0.w + x1 * v1.w + x2 * v2.w;
    ((float4*)d_nh)[i] = r;
}

__device__ __forceinline__ float fast_tanh(float u) {
    float r;
    asm("tanh.approx.f32 %0, %1;" : "=f"(r) : "f"(u));
    return r;
}

__global__ void __launch_bounds__(256) ecc_kernel(
    const float* __restrict__ ew, const float* __restrict__ fw,
    const int* __restrict__ eidx, const int* __restrict__ fidx,
    const int* __restrict__ batch)
{
    __shared__ float s_sig[Gg * Bb * DSLICE];          // 16 KB
    __shared__ float s_step[Gg * (Bb + 1) * DSLICE];   // 16.5 KB
    const int tid = threadIdx.x;
    for (int i = tid; i < Gg * Bb * DSLICE; i += 256) s_sig[i] = 0.f;
    for (int i = tid; i < Gg * (Bb + 1) * DSLICE; i += 256) s_step[i] = 0.f;
    __syncthreads();

    const int slice = blockIdx.y;
    const int dloc  = tid & (DSLICE - 1);
    const int dglob = slice * DSLICE + dloc;
    const int itemoff = tid >> 2;                      // 0..63
    const int base = blockIdx.x * ITEMS_PER_CHUNK;
    const int iend = min(M_TOTAL, base + ITEMS_PER_CHUNK);

    const float inv_dl = 31.f * 0.5f;

    for (int id = base + itemoff; id < iend; id += 64) {
        float h, sign; int g;
        if (id < Nn) {
            h = d_nh[id * Dd + dglob];
            g = batch[id];
            sign = 1.f;
        } else if (id < Nn + Ee) {
            int e = id - Nn;
            int a = eidx[e];
            int b = eidx[Ee + e];
            h = fmaxf(d_nh[a * Dd + dglob], d_nh[b * Dd + dglob]) * ew[e];
            g = batch[a];
            sign = -1.f;
        } else {
            int f = id - Nn - Ee;
            int a = fidx[f];
            int b = fidx[Ff + f];
            int c = fidx[2 * Ff + f];
            h = fmaxf(fmaxf(d_nh[a * Dd + dglob], d_nh[b * Dd + dglob]),
                      d_nh[c * Dd + dglob]) * fw[f];
            g = batch[a];
            sign = 1.f;
        }

        // crossing position in bump space; fixed 4-bump window floor(t)-1 .. floor(t)+2
        float t = fmaf(h, inv_dl, inv_dl);
        float bff = floorf(t);
        int bf = (int)bff;
        int b_end = min(max(bf + 3, 0), Bb);

        float shalf = 0.5f * sign;
        float u = (bff - 1.0f - t) * C_HALF;
        float* sig_base = &s_sig[(g * Bb) * DSLICE + dloc];
        #pragma unroll
        for (int j = 0; j < 4; ++j) {
            int b = bf - 1 + j;
            float val = fmaf(shalf, fast_tanh(u), shalf);
            if ((unsigned)b < (unsigned)Bb) {
                atomicAdd(sig_base + b * DSLICE, val);
            }
            u += C_HALF;
        }
        atomicAdd(&s_step[(g * (Bb + 1) + b_end) * DSLICE + dloc], sign);
    }
    __syncthreads();

    for (int i = tid; i < Gg * Bb * DSLICE; i += 256) {
        float vsum = s_sig[i];
        if (vsum != 0.f) {
            int d0 = i & (DSLICE - 1);
            int gb = i / DSLICE;
            atomicAdd(&d_sig[gb * Dd + slice * DSLICE + d0], vsum);
        }
    }
    for (int i = tid; i < Gg * (Bb + 1) * DSLICE; i += 256) {
        float vsum = s_step[i];
        if (vsum != 0.f) {
            int d0 = i & (DSLICE - 1);
            int gb = i / DSLICE;
            atomicAdd(&d_step[gb * Dd + slice * DSLICE + d0], vsum);
        }
    }
}

// fused combine + first GEMM layer, split-K over bump chunks.
// grid: (KC, JG); block 256.  Each block: 4 bumps (256 k) x 8 hidden x 32 graphs.
__global__ void __launch_bounds__(256) mlp1_kernel(
    const float* __restrict__ W1, float* __restrict__ flat)
{
    __shared__ float s_f[Gg * FSTRIDE];    // 32 x (256+4) floats = 33.3 KB
    __shared__ float s_w[8 * 256];         // 8 KB
    const int tid = threadIdx.x;
    const int kc = blockIdx.x;             // bump-chunk: bumps [kc*4, kc*4+4)
    const int jg = blockIdx.y;             // hidden units [jg*8, jg*8+8)
    const int bb0 = kc * 4;

    // --- step 1: reconstruct flat chunk (combine) into smem ---
    {
        int g = tid >> 3;
        int d0 = (tid & 7) * 8;
        #pragma unroll
        for (int dd = 0; dd < 8; ++dd) {
            int d = d0 + dd;
            const float* stp = &d_step[(g * (Bb + 1)) * Dd + d];
            float run = 0.f;
            for (int b = 0; b < bb0; ++b) run += stp[b * Dd];
            #pragma unroll
            for (int bi = 0; bi < 4; ++bi) {
                int b = bb0 + bi;
                run += stp[b * Dd];
                float val = d_sig[(g * Bb + b) * Dd + d] + run;
                s_f[g * FSTRIDE + bi * Dd + d] = val;
                if (jg == 0) flat[(g * Bb + b) * Dd + d] = val;
            }
        }
    }

    // --- step 2: load W1 tile (8 rows x 256 cols slice) ---
    {
        const int koff = bb0 * Dd;         // = kc*256
        #pragma unroll
        for (int r = 0; r < 2; ++r) {
            int idx = tid + r * 256;       // float4 index within 8x256 tile
            int row = idx >> 6, col = (idx & 63) << 2;
            ((float4*)s_w)[idx] = *(const float4*)&W1[(size_t)(jg * 8 + row) * (Bb * Dd) + koff + col];
        }
    }
    __syncthreads();

    // --- step 3: per-thread dot over 256 k ---
    const int j = tid >> 5;                // 0..7 (warp-uniform)
    const int g = tid & 31;                // lane
    const float4* wrow = (const float4*)&s_w[j * 256];
    const float* frow = &s_f[g * FSTRIDE];
    float acc = 0.f;
    #pragma unroll 8
    for (int k4 = 0; k4 < 64; ++k4) {
        float4 w = wrow[k4];
        float4 f = *(const float4*)&frow[k4 * 4];
        acc = fmaf(w.x, f.x, acc);
        acc = fmaf(w.y, f.y, acc);
        acc = fmaf(w.z, f.z, acc);
        acc = fmaf(w.w, f.w, acc);
    }
    atomicAdd(&d_h[g * HIDN + jg * 8 + j], acc);
}

// relu + second layer: one warp per output class, lane-parallel over k
__global__ void __launch_bounds__(320) mlp2_kernel(
    const float* __restrict__ W2, const float* __restrict__ b2,
    float* __restrict__ logits)
{
    const int g = blockIdx.x;
    const int w = threadIdx.x >> 5;        // 0..9 output class
    const int lane = threadIdx.x & 31;
    float acc = 0.f;
    #pragma unroll
    for (int k8 = 0; k8 < HIDN / 32; ++k8) {
        int k = k8 * 32 + lane;
        float hv = fmaxf(d_h[g * HIDN + k], 0.f);
        acc = fmaf(hv, W2[w * HIDN + k], acc);
    }
    #pragma unroll
    for (int off = 16; off; off >>= 1)
        acc += __shfl_xor_sync(0xffffffffu, acc, off);
    if (lane == 0) logits[g * NCc + w] = b2[w] + acc;
}

extern "C" void kernel_launch(void* const* d_in, const int* in_sizes, int n_in,
                              void* d_out, int out_size) {
    const float* x   = (const float*)d_in[0];
    const float* nw  = (const float*)d_in[1];
    const float* ew  = (const float*)d_in[2];
    const float* fw  = (const float*)d_in[3];
    const float* v   = (const float*)d_in[4];
    const float* W1  = (const float*)d_in[5];
    const float* b1  = (const float*)d_in[6];
    const float* W2  = (const float*)d_in[7];
    const float* b2  = (const float*)d_in[8];
    const int* eidx  = (const int*)d_in[9];
    const int* fidx  = (const int*)d_in[10];
    const int* batch = (const int*)d_in[11];

    float* out = (float*)d_out;
    float* logits = out;                 // [32, 10]
    float* flat   = out + Gg * NCc;      // [32, 2048]

    init_kernel<<<(Nn * (Dd / 4) + 255) / 256, 256>>>(x, nw, v, b1);
    dim3 grid(CHUNKS, NSLICE);
    ecc_kernel<<<grid, 256>>>(ew, fw, eidx, fidx, batch);
    dim3 mgrid(KC, JG);
    mlp1_kernel<<<mgrid, 256>>>(W1, flat);
    mlp2_kernel<<<Gg, 320>>>(W2, b2, logits);
}

// round 8
// speedup vs baseline: 2.3573x; 1.5400x over previous
#include <cuda_runtime.h>
#include <cuda_bf16.h>
#include <math.h>

#define Nn   16000
#define Ee   48000
#define Ff   32000
#define Dd   64
#define Bb   32
#define Gg   32
#define HIDN 256
#define NCc  10

#define DSLICE 4
#define NSLICE (Dd / DSLICE)          // 16
#define CHUNKS 40
#define M_TOTAL (Nn + Ee + Ff)        // 96000
#define ITEMS_PER_CHUNK ((M_TOTAL + CHUNKS - 1) / CHUNKS)  // 2400

#define C_HALF 3.2258064516f          // 0.5 * SCALE * (2/31)

#define KC 8                           // k-chunks (4 bumps each)
#define JG 32                          // j-groups (8 hidden each)
#define FPAD 4
#define FSTRIDE (256 + FPAD)           // padded flat-tile row stride (floats)

// scratch (device globals: no allocations allowed)
__device__ float d_nh[Nn * Dd];                    // 4 MB: per-node heights
__device__ float d_sig[Gg * Bb * Dd];              // windowed-sigmoid partials
__device__ float d_step[Gg * (Bb + 1) * Dd];       // step deltas
__device__ float d_h[Gg * HIDN];                   // hidden pre-activations

// fused: zero accumulators + seed d_h with b1 + compute node heights
__global__ void init_kernel(const float* __restrict__ x, const float* __restrict__ nw,
                            const float* __restrict__ v, const float* __restrict__ b1) {
    int i = blockIdx.x * blockDim.x + threadIdx.x;
    if (i < Gg * Bb * Dd) d_sig[i] = 0.f;
    if (i < Gg * (Bb + 1) * Dd) d_step[i] = 0.f;
    if (i < Gg * HIDN) d_h[i] = b1[i & (HIDN - 1)];
    if (i >= Nn * (Dd / 4)) return;
    int n = i >> 4, q = i & 15;
    float w = nw[n];
    float x0 = x[n * 3 + 0] * w, x1 = x[n * 3 + 1] * w, x2 = x[n * 3 + 2] * w;
    float4 v0 = ((const float4*)(v))[q];
    float4 v1 = ((const float4*)(v + Dd))[q];
    float4 v2 = ((const float4*)(v + 2 * Dd))[q];
    float4 r;
    r.x = x0 * v0.x + x1 * v1.x + x2 * v2.x;
    r.y = x0 * v0.y + x1 * v1.y + x2 * v2.y;
    r.z = x0 * v0.z + x1 * v1.z + x2 * v2.z;
    r.w = x0 * v0.w + x1 * v1.w + x2 * v2.w;
    ((float4*)d_nh)[i] = r;
}

__device__ __forceinline__ float fast_tanh(float u) {
    float r;
    asm("tanh.approx.f32 %0, %1;" : "=f"(r) : "f"(u));
    return r;
}

__global__ void __launch_bounds__(256) ecc_kernel(
    const float* __restrict__ ew, const float* __restrict__ fw,
    const int* __restrict__ eidx, const int* __restrict__ fidx,
    const int* __restrict__ batch)
{
    __shared__ float s_sig[Gg * Bb * DSLICE];          // 16 KB
    __shared__ float s_step[Gg * (Bb + 1) * DSLICE];   // 16.5 KB
    const int tid = threadIdx.x;
    for (int i = tid; i < Gg * Bb * DSLICE; i += 256) s_sig[i] = 0.f;
    for (int i = tid; i < Gg * (Bb + 1) * DSLICE; i += 256) s_step[i] = 0.f;
    __syncthreads();

    const int slice = blockIdx.y;
    const int dloc  = tid & (DSLICE - 1);
    const int dglob = slice * DSLICE + dloc;
    const int itemoff = tid >> 2;                      // 0..63
    const int base = blockIdx.x * ITEMS_PER_CHUNK;
    const int iend = min(M_TOTAL, base + ITEMS_PER_CHUNK);

    const float inv_dl = 31.f * 0.5f;

    for (int id = base + itemoff; id < iend; id += 64) {
        float h, sign; int g;
        if (id < Nn) {
            h = d_nh[id * Dd + dglob];
            g = batch[id];
            sign = 1.f;
        } else if (id < Nn + Ee) {
            int e = id - Nn;
            int a = eidx[e];
            int b = eidx[Ee + e];
            h = fmaxf(d_nh[a * Dd + dglob], d_nh[b * Dd + dglob]) * ew[e];
            g = batch[a];
            sign = -1.f;
        } else {
            int f = id - Nn - Ee;
            int a = fidx[f];
            int b = fidx[Ff + f];
            int c = fidx[2 * Ff + f];
            h = fmaxf(fmaxf(d_nh[a * Dd + dglob], d_nh[b * Dd + dglob]),
                      d_nh[c * Dd + dglob]) * fw[f];
            g = batch[a];
            sign = 1.f;
        }

        // 3-bump window centered on nearest bump: r-1, r, r+1 (max dist 1.5)
        float t = fmaf(h, inv_dl, inv_dl);
        float rff = floorf(t + 0.5f);
        int rr = (int)rff;
        int b_end = min(max(rr + 2, 0), Bb);

        float shalf = 0.5f * sign;
        float u = (rff - 1.0f - t) * C_HALF;
        float* sig_base = &s_sig[(g * Bb) * DSLICE + dloc];
        #pragma unroll
        for (int j = 0; j < 3; ++j) {
            int b = rr - 1 + j;
            float val = fmaf(shalf, fast_tanh(u), shalf);
            if ((unsigned)b < (unsigned)Bb) {
                atomicAdd(sig_base + b * DSLICE, val);
            }
            u += C_HALF;
        }
        atomicAdd(&s_step[(g * (Bb + 1) + b_end) * DSLICE + dloc], sign);
    }
    __syncthreads();

    for (int i = tid; i < Gg * Bb * DSLICE; i += 256) {
        float vsum = s_sig[i];
        if (vsum != 0.f) {
            int d0 = i & (DSLICE - 1);
            int gb = i / DSLICE;
            atomicAdd(&d_sig[gb * Dd + slice * DSLICE + d0], vsum);
        }
    }
    for (int i = tid; i < Gg * (Bb + 1) * DSLICE; i += 256) {
        float vsum = s_step[i];
        if (vsum != 0.f) {
            int d0 = i & (DSLICE - 1);
            int gb = i / DSLICE;
            atomicAdd(&d_step[gb * Dd + slice * DSLICE + d0], vsum);
        }
    }
}

// prefix over bumps: flat[g][b][d] = sig[g][b][d] + sum_{b'<=b} step[g][b'][d]
__global__ void combine_kernel(float* __restrict__ flat) {
    int g = blockIdx.x;
    int d = threadIdx.x;                // 64 threads
    float run = 0.f;
    const float* stp = &d_step[g * (Bb + 1) * Dd + d];
    const float* sgp = &d_sig[g * Bb * Dd + d];
    float* fp = &flat[g * Bb * Dd + d];
    #pragma unroll 8
    for (int b = 0; b < Bb; ++b) {
        run += stp[b * Dd];
        fp[b * Dd] = sgp[b * Dd] + run;
    }
}

// first GEMM layer, split-K over bump chunks.
// grid: (KC, JG); block 256.  Each block: 4 bumps (256 k) x 8 hidden x 32 graphs.
__global__ void __launch_bounds__(256) mlp1_kernel(
    const float* __restrict__ W1, const float* __restrict__ flat)
{
    __shared__ float s_f[Gg * FSTRIDE];    // 32 x (256+4) floats = 33.3 KB
    __shared__ float s_w[8 * 256];         // 8 KB
    const int tid = threadIdx.x;
    const int kc = blockIdx.x;             // bump-chunk: bumps [kc*4, kc*4+4)
    const int jg = blockIdx.y;             // hidden units [jg*8, jg*8+8)
    const int bb0 = kc * 4;

    // --- load flat chunk: rows g, cols 256 (bumps bb0..bb0+3 x 64 dirs) ---
    {
        // 256 threads x 8 float4 = 32 KB
        #pragma unroll
        for (int r = 0; r < 8; ++r) {
            int idx = tid + r * 256;           // float4 index in [0, 2048)
            int g = idx >> 6;                  // 64 float4 per row
            int c4 = idx & 63;
            float4 val = *(const float4*)&flat[(size_t)(g * Bb + bb0) * Dd + c4 * 4];
            *(float4*)&s_f[g * FSTRIDE + c4 * 4] = val;
        }
    }

    // --- load W1 tile (8 rows x 256 cols slice) ---
    {
        const int koff = bb0 * Dd;         // = kc*256
        #pragma unroll
        for (int r = 0; r < 2; ++r) {
            int idx = tid + r * 256;       // float4 index within 8x256 tile
            int row = idx >> 6, col = (idx & 63) << 2;
            ((float4*)s_w)[idx] = *(const float4*)&W1[(size_t)(jg * 8 + row) * (Bb * Dd) + koff + col];
        }
    }
    __syncthreads();

    // --- per-thread dot over 256 k ---
    const int j = tid >> 5;                // 0..7 (warp-uniform)
    const int g = tid & 31;                // lane
    const float4* wrow = (const float4*)&s_w[j * 256];
    const float* frow = &s_f[g * FSTRIDE];
    float acc = 0.f;
    #pragma unroll 8
    for (int k4 = 0; k4 < 64; ++k4) {
        float4 w = wrow[k4];
        float4 f = *(const float4*)&frow[k4 * 4];
        acc = fmaf(w.x, f.x, acc);
        acc = fmaf(w.y, f.y, acc);
        acc = fmaf(w.z, f.z, acc);
        acc = fmaf(w.w, f.w, acc);
    }
    atomicAdd(&d_h[g * HIDN + jg * 8 + j], acc);
}

// relu + second layer: one warp per output class, lane-parallel over k
__global__ void __launch_bounds__(320) mlp2_kernel(
    const float* __restrict__ W2, const float* __restrict__ b2,
    float* __restrict__ logits)
{
    const int g = blockIdx.x;
    const int w = threadIdx.x >> 5;        // 0..9 output class
    const int lane = threadIdx.x & 31;
    float acc = 0.f;
    #pragma unroll
    for (int k8 = 0; k8 < HIDN / 32; ++k8) {
        int k = k8 * 32 + lane;
        float hv = fmaxf(d_h[g * HIDN + k], 0.f);
        acc = fmaf(hv, W2[w * HIDN + k], acc);
    }
    #pragma unroll
    for (int off = 16; off; off >>= 1)
        acc += __shfl_xor_sync(0xffffffffu, acc, off);
    if (lane == 0) logits[g * NCc + w] = b2[w] + acc;
}

extern "C" void kernel_launch(void* const* d_in, const int* in_sizes, int n_in,
                              void* d_out, int out_size) {
    const float* x   = (const float*)d_in[0];
    const float* nw  = (const float*)d_in[1];
    const float* ew  = (const float*)d_in[2];
    const float* fw  = (const float*)d_in[3];
    const float* v   = (const float*)d_in[4];
    const float* W1  = (const float*)d_in[5];
    const float* b1  = (const float*)d_in[6];
    const float* W2  = (const float*)d_in[7];
    const float* b2  = (const float*)d_in[8];
    const int* eidx  = (const int*)d_in[9];
    const int* fidx  = (const int*)d_in[10];
    const int* batch = (const int*)d_in[11];

    float* out = (float*)d_out;
    float* logits = out;                 // [32, 10]
    float* flat   = out + Gg * NCc;      // [32, 2048]

    init_kernel<<<(Nn * (Dd / 4) + 255) / 256, 256>>>(x, nw, v, b1);
    dim3 grid(CHUNKS, NSLICE);
    ecc_kernel<<<grid, 256>>>(ew, fw, eidx, fidx, batch);
    combine_kernel<<<Gg, Dd>>>(flat);
    dim3 mgrid(KC, JG);
    mlp1_kernel<<<mgrid, 256>>>(W1, flat);
    mlp2_kernel<<<Gg, 320>>>(W2, b2, logits);
}